// round 5
// baseline (speedup 1.0000x reference)
#include <cuda_runtime.h>
#include <cuda_bf16.h>
#include <cuda_fp8.h>
#include <stdint.h>

// ============================================================================
// VideoContrastiveLoss on GB300 (sm_103 family target -> mma.sync path).
// Round 5: FP8 (e4m3) GEMM via mma.sync.m16n8k32 (2x MACs/instr vs bf16),
// upper-triangular symmetry (2080 of 4096 tiles), fixed-shift sum-of-exp.
// Positive logits computed EXACTLY in fp32 from raw input (separate kernel),
// so fp8 error only perturbs the log-sum term (~3e-5 relative on the loss).
// ============================================================================

#define N_ROWS 8192
#define DIM    1024
#define TILE   128
#define NT64   64                        // 8192/128
#define N_CTAS (NT64 * (NT64 + 1) / 2)   // 2080 upper-tri tiles
#define NKC    16                        // 1024 / 64 fp8 per chunk
#define STAGES 4
#define A_BYTES (TILE * 64)              // 128 rows x 64 fp8 (64B rows)
#define STAGE_BYTES (2 * A_BYTES)        // 16384
#define SMEM_K2 (STAGES * STAGE_BYTES)   // 65536
#define INV_T  14.2857142857142857f
#define SHIFT  16.0f

__device__ uint8_t g_f8[N_ROWS * DIM];           // normalized e4m3, row-major
__device__ float g_rowpart[N_ROWS * NT64];
__device__ float g_colpart[N_ROWS * NT64];
__device__ float g_pos[N_ROWS];
__device__ float g_rowloss[N_ROWS];

// ---------------------------------------------------------------------------
__device__ __forceinline__ uint32_t smem_u32(const void* p) {
    uint32_t a;
    asm("{ .reg .u64 t; cvta.to.shared.u64 t, %1; cvt.u32.u64 %0, t; }"
        : "=r"(a) : "l"(p));
    return a;
}
__device__ __forceinline__ void cp16(uint32_t dst, const void* src) {
    asm volatile("cp.async.cg.shared.global [%0], [%1], 16;"
                 :: "r"(dst), "l"(src) : "memory");
}
__device__ __forceinline__ void cp_commit() {
    asm volatile("cp.async.commit_group;" ::: "memory");
}
template <int N> __device__ __forceinline__ void cp_wait() {
    asm volatile("cp.async.wait_group %0;" :: "n"(N) : "memory");
}
__device__ __forceinline__ void ldsm4(uint32_t& r0, uint32_t& r1, uint32_t& r2,
                                      uint32_t& r3, uint32_t addr) {
    asm volatile("ldmatrix.sync.aligned.m8n8.x4.shared.b16 {%0,%1,%2,%3}, [%4];"
                 : "=r"(r0), "=r"(r1), "=r"(r2), "=r"(r3) : "r"(addr));
}
__device__ __forceinline__ void mma16832(float& c0, float& c1, float& c2, float& c3,
                                         uint32_t a0, uint32_t a1, uint32_t a2,
                                         uint32_t a3, uint32_t b0, uint32_t b1) {
    asm volatile(
        "mma.sync.aligned.m16n8k32.row.col.f32.e4m3.e4m3.f32 "
        "{%0,%1,%2,%3}, {%4,%5,%6,%7}, {%8,%9}, {%0,%1,%2,%3};"
        : "+f"(c0), "+f"(c1), "+f"(c2), "+f"(c3)
        : "r"(a0), "r"(a1), "r"(a2), "r"(a3), "r"(b0), "r"(b1));
}
// XOR swizzle for 64B rows (4 x 16B quads): quad' = quad ^ ((row>>1)&3)
__device__ __forceinline__ uint32_t sw_off(int r, int q) {
    return (uint32_t)(r * 64 + ((q ^ ((r >> 1) & 3)) << 4));
}

// ============================================================================
// Kernel 1: row L2-normalize fp32 -> e4m3 row-major.
// ============================================================================
__global__ __launch_bounds__(256) void vcl_norm_kernel(const float* __restrict__ f) {
    int row = blockIdx.x, tid = threadIdx.x;
    float4 x = reinterpret_cast<const float4*>(f)[row * (DIM / 4) + tid];
    float ss = x.x * x.x + x.y * x.y + x.z * x.z + x.w * x.w;
#pragma unroll
    for (int o = 16; o; o >>= 1) ss += __shfl_xor_sync(0xffffffffu, ss, o);
    __shared__ float red[8];
    if ((tid & 31) == 0) red[tid >> 5] = ss;
    __syncthreads();
    float tot = red[0] + red[1] + red[2] + red[3] + red[4] + red[5] + red[6] + red[7];
    float inv = 1.0f / fmaxf(sqrtf(tot), 1e-8f);

    __nv_fp8x2_storage_t lo = __nv_cvt_float2_to_fp8x2(
        make_float2(x.x * inv, x.y * inv), __NV_SATFINITE, __NV_E4M3);
    __nv_fp8x2_storage_t hi = __nv_cvt_float2_to_fp8x2(
        make_float2(x.z * inv, x.w * inv), __NV_SATFINITE, __NV_E4M3);
    uint32_t packed = (uint32_t)lo | ((uint32_t)hi << 16);
    reinterpret_cast<uint32_t*>(g_f8 + (size_t)row * DIM)[tid] = packed;
    // NOTE: any fixed k-permutation inside pairs cancels in A @ A^T.
}

// ============================================================================
// Kernel 1b: exact positive logits in fp32 from the RAW input.
// Warp w handles pair (w, w+4096): pos = dot/(max(|a|,eps)*max(|b|,eps))/T.
// ============================================================================
__global__ __launch_bounds__(256) void vcl_pos_kernel(const float* __restrict__ f) {
    int w = (blockIdx.x * 256 + threadIdx.x) >> 5;    // 0..4095 (grid 512)
    int l = threadIdx.x & 31;
    if (w >= N_ROWS / 2) return;
    const float4* a4 = reinterpret_cast<const float4*>(f + (size_t)w * DIM);
    const float4* b4 = reinterpret_cast<const float4*>(f + (size_t)(w + N_ROWS / 2) * DIM);
    float dot = 0.f, na = 0.f, nb = 0.f;
#pragma unroll
    for (int i = 0; i < DIM / 4 / 32; i++) {
        float4 a = a4[l + i * 32], b = b4[l + i * 32];
        dot = fmaf(a.x, b.x, fmaf(a.y, b.y, fmaf(a.z, b.z, fmaf(a.w, b.w, dot))));
        na  = fmaf(a.x, a.x, fmaf(a.y, a.y, fmaf(a.z, a.z, fmaf(a.w, a.w, na))));
        nb  = fmaf(b.x, b.x, fmaf(b.y, b.y, fmaf(b.z, b.z, fmaf(b.w, b.w, nb))));
    }
#pragma unroll
    for (int o = 16; o; o >>= 1) {
        dot += __shfl_xor_sync(0xffffffffu, dot, o);
        na  += __shfl_xor_sync(0xffffffffu, na, o);
        nb  += __shfl_xor_sync(0xffffffffu, nb, o);
    }
    if (l == 0) {
        float p = dot / (fmaxf(sqrtf(na), 1e-8f) * fmaxf(sqrtf(nb), 1e-8f)) * INV_T;
        g_pos[w] = p;
        g_pos[w + N_ROWS / 2] = p;
    }
}

// ============================================================================
// Kernel 2: upper-tri tile (it<=jt): S[128x128] = A_it @ A_jt^T in e4m3,
// fp32 accum; exp epilogue feeds row-side and col-side sums.
// ============================================================================
__global__ __launch_bounds__(256, 2) void vcl_mma_kernel() {
    extern __shared__ char smem[];
    __shared__ float rowbuf[TILE];
    __shared__ float colbuf[TILE];
    const uint32_t sb = smem_u32(smem);
    const int tid = threadIdx.x;
    const int wid = tid >> 5, l = tid & 31;
    const int wm = wid >> 2, wn = wid & 3;   // warp grid 2x4, warp tile 64x32

    int it = 0, rem = blockIdx.x;
    while (rem >= NT64 - it) { rem -= NT64 - it; it++; }
    const int jt = it + rem;
    const bool isdiag = (it == jt);

    auto issue = [&](int kc, int stage) {
        uint32_t base = sb + (uint32_t)stage * STAGE_BYTES;
        const uint8_t* gA = g_f8 + (size_t)(it * TILE) * DIM + kc * 64;
        const uint8_t* gB = g_f8 + (size_t)(jt * TILE) * DIM + kc * 64;
#pragma unroll
        for (int i = 0; i < 2; i++) {            // A: 512 quads / 256 thr
            int idx = tid + i * 256;
            int r = idx >> 2, q = idx & 3;
            cp16(base + sw_off(r, q), gA + (size_t)r * DIM + q * 16);
        }
#pragma unroll
        for (int i = 0; i < 2; i++) {            // B: 512 quads
            int idx = tid + i * 256;
            int r = idx >> 2, q = idx & 3;
            cp16(base + A_BYTES + sw_off(r, q), gB + (size_t)r * DIM + q * 16);
        }
        cp_commit();
    };

    float acc[4][4][4];
#pragma unroll
    for (int a = 0; a < 4; a++)
#pragma unroll
        for (int b = 0; b < 4; b++)
#pragma unroll
            for (int c = 0; c < 4; c++) acc[a][b][c] = 0.f;

    issue(0, 0); issue(1, 1); issue(2, 2);

    const int rA_in = (l & 7) + ((l >> 3) & 1) * 8;
    const int qA_hi = (l >> 4);
    const int rB_in = (l & 7) + ((l >> 4) ? 8 : 0);
    const int qB_hi = ((l >> 3) & 1);

    for (int kc = 0; kc < NKC; kc++) {
        cp_wait<STAGES - 2>();
        __syncthreads();
        if (kc + 3 < NKC) issue(kc + 3, (kc + 3) & (STAGES - 1));
        else cp_commit();

        uint32_t sA = sb + (uint32_t)(kc & (STAGES - 1)) * STAGE_BYTES;
        uint32_t sB = sA + A_BYTES;
#pragma unroll
        for (int kk = 0; kk < 2; kk++) {         // two k32 fp8 steps per 64B chunk
            uint32_t af[4][4], bf2[2][4];
#pragma unroll
            for (int mt = 0; mt < 4; mt++) {
                int r = wm * 64 + mt * 16 + rA_in;
                ldsm4(af[mt][0], af[mt][1], af[mt][2], af[mt][3],
                      sA + sw_off(r, kk * 2 + qA_hi));
            }
#pragma unroll
            for (int np = 0; np < 2; np++) {
                int r = wn * 32 + np * 16 + rB_in;
                ldsm4(bf2[np][0], bf2[np][1], bf2[np][2], bf2[np][3],
                      sB + sw_off(r, kk * 2 + qB_hi));
            }
#pragma unroll
            for (int mt = 0; mt < 4; mt++)
#pragma unroll
                for (int nt = 0; nt < 4; nt++)
                    mma16832(acc[mt][nt][0], acc[mt][nt][1], acc[mt][nt][2],
                             acc[mt][nt][3],
                             af[mt][0], af[mt][1], af[mt][2], af[mt][3],
                             bf2[nt >> 1][(nt & 1) * 2],
                             bf2[nt >> 1][(nt & 1) * 2 + 1]);
        }
    }
    cp_wait<0>();

    // ---- epilogue: exp-sum, exact diag skip ----
    if (tid < TILE) rowbuf[tid] = 0.f;
    else colbuf[tid - TILE] = 0.f;
    __syncthreads();

    const int m0 = it * TILE + wm * 64;
    const int n0 = jt * TILE + wn * 32;
    const int lr = l >> 2;
    const int lc = 2 * (l & 3);
    float colacc[8];
#pragma unroll
    for (int i = 0; i < 8; i++) colacc[i] = 0.f;

#pragma unroll
    for (int mt = 0; mt < 4; mt++) {
#pragma unroll
        for (int h = 0; h < 2; h++) {
            int gr = m0 + mt * 16 + lr + h * 8;
            float s = 0.f;
#pragma unroll
            for (int nt = 0; nt < 4; nt++) {
#pragma unroll
                for (int cc = 0; cc < 2; cc++) {
                    int gc = n0 + nt * 8 + lc + cc;
                    float v = acc[mt][nt][h * 2 + cc];
                    float e = __expf(fmaf(v, INV_T, -SHIFT));
                    e = (gc == gr) ? 0.f : e;     // exact diagonal skip
                    s += e;
                    colacc[nt * 2 + cc] += e;
                }
            }
            s += __shfl_xor_sync(0xffffffffu, s, 1);
            s += __shfl_xor_sync(0xffffffffu, s, 2);
            if ((l & 3) == 0)
                atomicAdd(&rowbuf[wm * 64 + mt * 16 + lr + h * 8], s);
        }
    }
    if (!isdiag) {
#pragma unroll
        for (int i = 0; i < 8; i++) {
            float v = colacc[i];
            v += __shfl_xor_sync(0xffffffffu, v, 4);
            v += __shfl_xor_sync(0xffffffffu, v, 8);
            v += __shfl_xor_sync(0xffffffffu, v, 16);
            colacc[i] = v;
        }
        if (l < 4) {
#pragma unroll
            for (int nt = 0; nt < 4; nt++)
#pragma unroll
                for (int cc = 0; cc < 2; cc++)
                    atomicAdd(&colbuf[wn * 32 + nt * 8 + 2 * l + cc],
                              colacc[nt * 2 + cc]);
        }
    }
    __syncthreads();
    if (tid < TILE) {
        g_rowpart[(size_t)(it * TILE + tid) * NT64 + jt] = rowbuf[tid];
    } else if (!isdiag) {
        int c = tid - TILE;
        g_colpart[(size_t)(jt * TILE + c) * NT64 + it] = colbuf[c];
    }
}

// ============================================================================
// Kernel 3a: per-row loss_i = SHIFT + log(sum of gated partials) - pos_i
// ============================================================================
__global__ __launch_bounds__(256) void vcl_rowloss_kernel() {
    int wid = (blockIdx.x * 256 + threadIdx.x) >> 5;
    int l = threadIdx.x & 31;
    for (int row = wid; row < N_ROWS; row += 256) {
        int tr = row >> 7;
        float s = 0.f;
#pragma unroll
        for (int g = l; g < NT64; g += 32)
            s += (g >= tr) ? g_rowpart[(size_t)row * NT64 + g]
                           : g_colpart[(size_t)row * NT64 + g];
#pragma unroll
        for (int o = 16; o; o >>= 1) s += __shfl_xor_sync(0xffffffffu, s, o);
        if (l == 0) g_rowloss[row] = (SHIFT + logf(s)) - g_pos[row];
    }
}

// ============================================================================
// Kernel 3b: final mean (single block, fixed order)
// ============================================================================
__global__ __launch_bounds__(1024) void vcl_reduce_kernel(float* __restrict__ out) {
    int tid = threadIdx.x;
    float local = 0.f;
#pragma unroll
    for (int i = 0; i < N_ROWS / 1024; i++) local += g_rowloss[tid + i * 1024];
#pragma unroll
    for (int o = 16; o; o >>= 1) local += __shfl_xor_sync(0xffffffffu, local, o);
    __shared__ float red[32];
    if ((tid & 31) == 0) red[tid >> 5] = local;
    __syncthreads();
    if (tid < 32) {
        float v = red[tid];
#pragma unroll
        for (int o = 16; o; o >>= 1) v += __shfl_xor_sync(0xffffffffu, v, o);
        if (tid == 0) out[0] = v * (1.0f / (float)N_ROWS);
    }
}

// ============================================================================
extern "C" void kernel_launch(void* const* d_in, const int* in_sizes, int n_in,
                              void* d_out, int out_size) {
    const float* feat = (const float*)d_in[0];
    float* out = (float*)d_out;

    cudaFuncSetAttribute(vcl_mma_kernel,
                         cudaFuncAttributeMaxDynamicSharedMemorySize, SMEM_K2);

    vcl_norm_kernel<<<N_ROWS, 256>>>(feat);
    vcl_pos_kernel<<<512, 256>>>(feat);
    vcl_mma_kernel<<<N_CTAS, 256, SMEM_K2>>>();
    vcl_rowloss_kernel<<<32, 256>>>();
    vcl_reduce_kernel<<<1, 1024>>>(out);
}

// round 6
// speedup vs baseline: 1.7816x; 1.7816x over previous
#include <cuda_runtime.h>
#include <cuda_bf16.h>
#include <stdint.h>

// ============================================================================
// VideoContrastiveLoss on GB300 (sm_103 family target -> mma.sync HMMA path).
// Round 6: revert FP8 (regressed 1.6x: legacy-path QMMA != 2x HMMA rate).
// Back to R3 bf16 symmetric kernel (221us) + fix the latency-bound rowloss
// tail (45.8us @ occ 12.6% -> ~5us via 8x more warps).
//   sim = normalize(f) @ normalize(f)^T / 0.07, diag=-inf, CE vs label i^4096.
// Upper-triangular tiles only; exp feeds row-side AND col-side sums.
// Fixed-shift softmax (logits <= 1/0.07 < 16), exact diagonal skip.
// ============================================================================

#define N_ROWS 8192
#define DIM    1024
#define TILE   128
#define NT64   64                    // 8192/128 tiles per side
#define N_CTAS (NT64 * (NT64 + 1) / 2)   // 2080 upper-tri tiles
#define KC     32
#define NKC    (DIM / KC)            // 32
#define STAGES 4
#define A_BYTES (TILE * 64)          // 128 rows x 32 bf16 (64B)
#define STAGE_BYTES (2 * A_BYTES)    // 16384
#define SMEM_K2 (STAGES * STAGE_BYTES)   // 65536
#define INV_T  14.2857142857142857f
#define SHIFT  16.0f

__device__ __nv_bfloat16 g_fn[N_ROWS * DIM];     // normalized bf16 row-major
__device__ float g_rowpart[N_ROWS * NT64];       // tile (tr, g>=tr) row-side sums
__device__ float g_colpart[N_ROWS * NT64];       // tile (g<tr, tr) col-side sums
__device__ float g_pos[N_ROWS];
__device__ float g_rowloss[N_ROWS];

// ---------------------------------------------------------------------------
__device__ __forceinline__ uint32_t smem_u32(const void* p) {
    uint32_t a;
    asm("{ .reg .u64 t; cvta.to.shared.u64 t, %1; cvt.u32.u64 %0, t; }"
        : "=r"(a) : "l"(p));
    return a;
}
__device__ __forceinline__ void cp16(uint32_t dst, const void* src) {
    asm volatile("cp.async.cg.shared.global [%0], [%1], 16;"
                 :: "r"(dst), "l"(src) : "memory");
}
__device__ __forceinline__ void cp_commit() {
    asm volatile("cp.async.commit_group;" ::: "memory");
}
template <int N> __device__ __forceinline__ void cp_wait() {
    asm volatile("cp.async.wait_group %0;" :: "n"(N) : "memory");
}
__device__ __forceinline__ void ldsm4(uint32_t& r0, uint32_t& r1, uint32_t& r2,
                                      uint32_t& r3, uint32_t addr) {
    asm volatile("ldmatrix.sync.aligned.m8n8.x4.shared.b16 {%0,%1,%2,%3}, [%4];"
                 : "=r"(r0), "=r"(r1), "=r"(r2), "=r"(r3) : "r"(addr));
}
__device__ __forceinline__ void mma16816(float& c0, float& c1, float& c2, float& c3,
                                         uint32_t a0, uint32_t a1, uint32_t a2,
                                         uint32_t a3, uint32_t b0, uint32_t b1) {
    asm volatile(
        "mma.sync.aligned.m16n8k16.row.col.f32.bf16.bf16.f32 "
        "{%0,%1,%2,%3}, {%4,%5,%6,%7}, {%8,%9}, {%0,%1,%2,%3};"
        : "+f"(c0), "+f"(c1), "+f"(c2), "+f"(c3)
        : "r"(a0), "r"(a1), "r"(a2), "r"(a3), "r"(b0), "r"(b1));
}
// XOR swizzle for 64B rows (4 x 16B quads): quad' = quad ^ ((row>>1)&3)
__device__ __forceinline__ uint32_t sw_off(int r, int q) {
    return (uint32_t)(r * 64 + ((q ^ ((r >> 1) & 3)) << 4));
}

// ============================================================================
// Kernel 1: row L2-normalize fp32 -> bf16 row-major.
// ============================================================================
__global__ __launch_bounds__(256) void vcl_norm_kernel(const float* __restrict__ f) {
    int row = blockIdx.x, tid = threadIdx.x;
    float4 x = reinterpret_cast<const float4*>(f)[row * (DIM / 4) + tid];
    float ss = x.x * x.x + x.y * x.y + x.z * x.z + x.w * x.w;
#pragma unroll
    for (int o = 16; o; o >>= 1) ss += __shfl_xor_sync(0xffffffffu, ss, o);
    __shared__ float red[8];
    if ((tid & 31) == 0) red[tid >> 5] = ss;
    __syncthreads();
    float tot = red[0] + red[1] + red[2] + red[3] + red[4] + red[5] + red[6] + red[7];
    float inv = 1.0f / fmaxf(sqrtf(tot), 1e-8f);
    __nv_bfloat162 lo = __floats2bfloat162_rn(x.x * inv, x.y * inv);
    __nv_bfloat162 hi = __floats2bfloat162_rn(x.z * inv, x.w * inv);
    uint2 v;
    v.x = reinterpret_cast<uint32_t&>(lo);
    v.y = reinterpret_cast<uint32_t&>(hi);
    reinterpret_cast<uint2*>(g_fn)[row * (DIM / 4) + tid] = v;
}

// ============================================================================
// Kernel 2: upper-tri tile (it<=jt): S[128x128] = A_it @ A_jt^T, exp epilogue
// feeding row-side (rows of it-block) and col-side (rows of jt-block) sums.
// ============================================================================
__global__ __launch_bounds__(256, 2) void vcl_mma_kernel() {
    extern __shared__ char smem[];
    __shared__ float rowbuf[TILE];
    __shared__ float colbuf[TILE];
    const uint32_t sb = smem_u32(smem);
    const int tid = threadIdx.x;
    const int wid = tid >> 5, l = tid & 31;
    const int wm = wid >> 2, wn = wid & 3;   // warp grid 2x4, warp tile 64x32

    // decode linear upper-tri index -> (it, jt), it<=jt
    int it = 0, rem = blockIdx.x;
    while (rem >= NT64 - it) { rem -= NT64 - it; it++; }
    const int jt = it + rem;
    const bool isdiag = (it == jt);

    auto issue = [&](int kc, int stage) {
        uint32_t base = sb + (uint32_t)stage * STAGE_BYTES;
        const __nv_bfloat16* gA = g_fn + (size_t)(it * TILE) * DIM + kc * KC;
        const __nv_bfloat16* gB = g_fn + (size_t)(jt * TILE) * DIM + kc * KC;
#pragma unroll
        for (int i = 0; i < 2; i++) {            // A: 512 quads / 256 thr
            int idx = tid + i * 256;
            int r = idx >> 2, q = idx & 3;
            cp16(base + sw_off(r, q), gA + (size_t)r * DIM + q * 8);
        }
#pragma unroll
        for (int i = 0; i < 2; i++) {            // B: 512 quads
            int idx = tid + i * 256;
            int r = idx >> 2, q = idx & 3;
            cp16(base + A_BYTES + sw_off(r, q), gB + (size_t)r * DIM + q * 8);
        }
        cp_commit();
    };

    float acc[4][4][4];
#pragma unroll
    for (int a = 0; a < 4; a++)
#pragma unroll
        for (int b = 0; b < 4; b++)
#pragma unroll
            for (int c = 0; c < 4; c++) acc[a][b][c] = 0.f;

    issue(0, 0); issue(1, 1); issue(2, 2);

    const int rA_in = (l & 7) + ((l >> 3) & 1) * 8;
    const int qA_hi = (l >> 4);
    const int rB_in = (l & 7) + ((l >> 4) ? 8 : 0);
    const int qB_hi = ((l >> 3) & 1);

    for (int kc = 0; kc < NKC; kc++) {
        cp_wait<STAGES - 2>();
        __syncthreads();
        if (kc + 3 < NKC) issue(kc + 3, (kc + 3) & (STAGES - 1));
        else cp_commit();

        uint32_t sA = sb + (uint32_t)(kc & (STAGES - 1)) * STAGE_BYTES;
        uint32_t sB = sA + A_BYTES;
#pragma unroll
        for (int kk = 0; kk < 2; kk++) {
            uint32_t af[4][4], bf2[2][4];
#pragma unroll
            for (int mt = 0; mt < 4; mt++) {
                int r = wm * 64 + mt * 16 + rA_in;
                ldsm4(af[mt][0], af[mt][1], af[mt][2], af[mt][3],
                      sA + sw_off(r, kk * 2 + qA_hi));
            }
#pragma unroll
            for (int np = 0; np < 2; np++) {
                int r = wn * 32 + np * 16 + rB_in;
                ldsm4(bf2[np][0], bf2[np][1], bf2[np][2], bf2[np][3],
                      sB + sw_off(r, kk * 2 + qB_hi));
            }
#pragma unroll
            for (int mt = 0; mt < 4; mt++)
#pragma unroll
                for (int nt = 0; nt < 4; nt++)
                    mma16816(acc[mt][nt][0], acc[mt][nt][1], acc[mt][nt][2],
                             acc[mt][nt][3],
                             af[mt][0], af[mt][1], af[mt][2], af[mt][3],
                             bf2[nt >> 1][(nt & 1) * 2],
                             bf2[nt >> 1][(nt & 1) * 2 + 1]);
        }
    }
    cp_wait<0>();

    // ---- epilogue ----
    if (tid < TILE) rowbuf[tid] = 0.f;
    else colbuf[tid - TILE] = 0.f;
    __syncthreads();

    const int m0 = it * TILE + wm * 64;
    const int n0 = jt * TILE + wn * 32;
    const int lr = l >> 2;
    const int lc = 2 * (l & 3);
    float colacc[8];
#pragma unroll
    for (int i = 0; i < 8; i++) colacc[i] = 0.f;

#pragma unroll
    for (int mt = 0; mt < 4; mt++) {
#pragma unroll
        for (int h = 0; h < 2; h++) {
            int gr = m0 + mt * 16 + lr + h * 8;
            int lab = gr ^ (N_ROWS / 2);
            float s = 0.f;
#pragma unroll
            for (int nt = 0; nt < 4; nt++) {
#pragma unroll
                for (int cc = 0; cc < 2; cc++) {
                    int gc = n0 + nt * 8 + lc + cc;
                    float v = acc[mt][nt][h * 2 + cc];
                    float e = __expf(fmaf(v, INV_T, -SHIFT));
                    if (gc == lab) {         // pair (gr,gc): capture both rows
                        float p = v * INV_T;
                        g_pos[gr] = p;
                        g_pos[gc] = p;       // never a diag tile (|gr-gc|=4096)
                    }
                    e = (gc == gr) ? 0.f : e;
                    s += e;
                    colacc[nt * 2 + cc] += e;
                }
            }
            // row reduce over the 4 lanes sharing this row
            s += __shfl_xor_sync(0xffffffffu, s, 1);
            s += __shfl_xor_sync(0xffffffffu, s, 2);
            if ((l & 3) == 0)
                atomicAdd(&rowbuf[wm * 64 + mt * 16 + lr + h * 8], s);
        }
    }
    if (!isdiag) {
        // col reduce: lanes {l, l^4, l^8, l^16} share the same 8 columns
#pragma unroll
        for (int i = 0; i < 8; i++) {
            float v = colacc[i];
            v += __shfl_xor_sync(0xffffffffu, v, 4);
            v += __shfl_xor_sync(0xffffffffu, v, 8);
            v += __shfl_xor_sync(0xffffffffu, v, 16);
            colacc[i] = v;
        }
        if (l < 4) {
#pragma unroll
            for (int nt = 0; nt < 4; nt++)
#pragma unroll
                for (int cc = 0; cc < 2; cc++)
                    atomicAdd(&colbuf[wn * 32 + nt * 8 + 2 * l + cc],
                              colacc[nt * 2 + cc]);
        }
    }
    __syncthreads();
    if (tid < TILE) {
        g_rowpart[(size_t)(it * TILE + tid) * NT64 + jt] = rowbuf[tid];
    } else if (!isdiag) {
        int c = tid - TILE;
        g_colpart[(size_t)(jt * TILE + c) * NT64 + it] = colbuf[c];
    }
}

// ============================================================================
// Kernel 3a: per-row loss_i = SHIFT + log(sum of gated partials) - pos_i
// 256 blocks x 8 warps = 2048 warps (4 rows/warp) -> latency fully hidden.
// ============================================================================
__global__ __launch_bounds__(256) void vcl_rowloss_kernel() {
    int wid = (blockIdx.x * 256 + threadIdx.x) >> 5;   // 0..2047
    int l = threadIdx.x & 31;
    for (int row = wid; row < N_ROWS; row += 2048) {
        int tr = row >> 7;
        float s = 0.f;
#pragma unroll
        for (int g = l; g < NT64; g += 32)
            s += (g >= tr) ? g_rowpart[(size_t)row * NT64 + g]
                           : g_colpart[(size_t)row * NT64 + g];
#pragma unroll
        for (int o = 16; o; o >>= 1) s += __shfl_xor_sync(0xffffffffu, s, o);
        if (l == 0) g_rowloss[row] = (SHIFT + logf(s)) - g_pos[row];
    }
}

// ============================================================================
// Kernel 3b: final mean (single block, fixed order)
// ============================================================================
__global__ __launch_bounds__(1024) void vcl_reduce_kernel(float* __restrict__ out) {
    int tid = threadIdx.x;
    float local = 0.f;
#pragma unroll
    for (int i = 0; i < N_ROWS / 1024; i++) local += g_rowloss[tid + i * 1024];
#pragma unroll
    for (int o = 16; o; o >>= 1) local += __shfl_xor_sync(0xffffffffu, local, o);
    __shared__ float red[32];
    if ((tid & 31) == 0) red[tid >> 5] = local;
    __syncthreads();
    if (tid < 32) {
        float v = red[tid];
#pragma unroll
        for (int o = 16; o; o >>= 1) v += __shfl_xor_sync(0xffffffffu, v, o);
        if (tid == 0) out[0] = v * (1.0f / (float)N_ROWS);
    }
}

// ============================================================================
extern "C" void kernel_launch(void* const* d_in, const int* in_sizes, int n_in,
                              void* d_out, int out_size) {
    const float* feat = (const float*)d_in[0];
    float* out = (float*)d_out;

    cudaFuncSetAttribute(vcl_mma_kernel,
                         cudaFuncAttributeMaxDynamicSharedMemorySize, SMEM_K2);

    vcl_norm_kernel<<<N_ROWS, 256>>>(feat);
    vcl_mma_kernel<<<N_CTAS, 256, SMEM_K2>>>();
    vcl_rowloss_kernel<<<256, 256>>>();
    vcl_reduce_kernel<<<1, 1024>>>(out);
}